// round 2
// baseline (speedup 1.0000x reference)
#include <cuda_runtime.h>
#include <math.h>

#define NMAX 100000
#define EMAX 1600000
#define HCD 128
#define NGRP 64
#define NCLS 10

typedef unsigned long long ull;

// ---------------- static device scratch ----------------
__device__ float  g_h[(size_t)NMAX * HCD];
__device__ float  g_act[(size_t)NMAX * HCD];
__device__ int    g_srcs[EMAX];
__device__ float4 g_le[3][EMAX];
__device__ int    g_cnt[NMAX];
__device__ int    g_rowptr[NMAX + 1];
__device__ int    g_woff[NMAX];
__device__ int    g_bsum[1024];
__device__ int    g_boff[1024];
__device__ float4 g_ls[NMAX];
__device__ float4 g_ld[NMAX];
__device__ float  g_ve[3 * 16 * 4];
__device__ float  g_leself[12];
__device__ float  g_easum[16];
__device__ float  g_gemb[NGRP * HCD];
__device__ float  g_gcnt[NGRP];

// ---------------- helpers ----------------
__device__ __forceinline__ float lrelu(float x) { return x > 0.f ? x : 0.2f * x; }

__device__ __forceinline__ ull pk2(float x, float y) {
    ull r;
    asm("mov.b64 %0, {%1,%2};" : "=l"(r) : "r"(__float_as_uint(x)), "r"(__float_as_uint(y)));
    return r;
}
__device__ __forceinline__ void fma2(ull& d, ull a, ull b) {
    asm("fma.rn.f32x2 %0, %1, %2, %0;" : "+l"(d) : "l"(a), "l"(b));
}
__device__ __forceinline__ float lo2(ull v) { return __uint_as_float((unsigned)(v & 0xffffffffull)); }
__device__ __forceinline__ float hi2(ull v) { return __uint_as_float((unsigned)(v >> 32)); }

// ---------------- init / preprocessing ----------------
__global__ void k_zero(int n) {
    int i = blockIdx.x * blockDim.x + threadIdx.x;
    if (i < n) g_cnt[i] = 0;
    if (i < 16) g_easum[i] = 0.f;
    if (i < NGRP * HCD) g_gemb[i] = 0.f;
    if (i < NGRP) g_gcnt[i] = 0.f;
}

__global__ void k_hist(const int* __restrict__ dst, int E) {
    int e = blockIdx.x * blockDim.x + threadIdx.x;
    if (e < E) atomicAdd(&g_cnt[dst[e]], 1);
}

__global__ void k_scanA(int n) {
    __shared__ int sh[256];
    int base = blockIdx.x * 1024;
    int s = 0;
    for (int i = threadIdx.x; i < 1024; i += 256) {
        int idx = base + i;
        if (idx < n) s += g_cnt[idx];
    }
    sh[threadIdx.x] = s; __syncthreads();
    for (int d = 128; d > 0; d >>= 1) {
        if (threadIdx.x < d) sh[threadIdx.x] += sh[threadIdx.x + d];
        __syncthreads();
    }
    if (threadIdx.x == 0) g_bsum[blockIdx.x] = sh[0];
}

__global__ void k_scanB(int nchunks, int n) {
    if (threadIdx.x == 0) {
        int run = 0;
        for (int b = 0; b < nchunks; b++) { g_boff[b] = run; run += g_bsum[b]; }
        g_rowptr[n] = run;
    }
}

__global__ void k_scanC(int n) {
    __shared__ int sh[256];
    int base = blockIdx.x * 1024 + threadIdx.x * 4;
    int v[4];
#pragma unroll
    for (int j = 0; j < 4; j++) { int idx = base + j; v[j] = (idx < n) ? g_cnt[idx] : 0; }
    int s = v[0] + v[1] + v[2] + v[3];
    sh[threadIdx.x] = s; __syncthreads();
    for (int d = 1; d < 256; d <<= 1) {
        int add = (threadIdx.x >= (unsigned)d) ? sh[threadIdx.x - d] : 0;
        __syncthreads();
        sh[threadIdx.x] += add;
        __syncthreads();
    }
    int off = g_boff[blockIdx.x] + sh[threadIdx.x] - s;
#pragma unroll
    for (int j = 0; j < 4; j++) {
        int idx = base + j;
        if (idx < n) { g_rowptr[idx] = off; g_woff[idx] = off; off += v[j]; }
    }
}

__global__ void k_easum(const float4* __restrict__ ea4, int E) {
    float s[16];
#pragma unroll
    for (int f = 0; f < 16; f++) s[f] = 0.f;
    for (int e = blockIdx.x * blockDim.x + threadIdx.x; e < E; e += gridDim.x * blockDim.x) {
#pragma unroll
        for (int q = 0; q < 4; q++) {
            float4 v = ea4[(size_t)e * 4 + q];
            s[q * 4 + 0] += v.x; s[q * 4 + 1] += v.y; s[q * 4 + 2] += v.z; s[q * 4 + 3] += v.w;
        }
    }
    __shared__ float sm[16];
    if (threadIdx.x < 16) sm[threadIdx.x] = 0.f;
    __syncthreads();
#pragma unroll
    for (int f = 0; f < 16; f++) atomicAdd(&sm[f], s[f]);
    __syncthreads();
    if (threadIdx.x < 16) atomicAdd(&g_easum[threadIdx.x], sm[threadIdx.x]);
}

__global__ void k_ve(const float* We1, const float* aE1,
                     const float* We2, const float* aE2,
                     const float* We3, const float* aE3, int E) {
    int idx = threadIdx.x;
    const float* Wes[3] = { We1, We2, We3 };
    const float* aEs[3] = { aE1, aE2, aE3 };
    if (idx < 192) {
        int l = idx >> 6, f = (idx >> 2) & 15, h = idx & 3;
        const float* We = Wes[l]; const float* aE = aEs[l];
        float s = 0.f;
        for (int c = 0; c < 32; c++) s += We[f * 128 + h * 32 + c] * aE[h * 32 + c];
        g_ve[l * 64 + f * 4 + h] = s;
    }
    __syncthreads();
    if (idx < 12) {
        int l = idx >> 2, h = idx & 3;
        float inv = 1.f / (float)E;
        float s = 0.f;
        for (int f = 0; f < 16; f++) s += g_easum[f] * inv * g_ve[l * 64 + f * 4 + h];
        g_leself[l * 4 + h] = s;
    }
}

__global__ void k_scatter(const int* __restrict__ src, const int* __restrict__ dst,
                          const float4* __restrict__ ea4, int E) {
    int e = blockIdx.x * blockDim.x + threadIdx.x;
    if (e >= E) return;
    int d = dst[e];
    int pos = atomicAdd(&g_woff[d], 1);
    g_srcs[pos] = src[e];
    float a[16];
#pragma unroll
    for (int q = 0; q < 4; q++) {
        float4 v = ea4[(size_t)e * 4 + q];
        a[q * 4 + 0] = v.x; a[q * 4 + 1] = v.y; a[q * 4 + 2] = v.z; a[q * 4 + 3] = v.w;
    }
#pragma unroll
    for (int l = 0; l < 3; l++) {
        const float4* vel = (const float4*)&g_ve[l * 64];
        float r0 = 0.f, r1 = 0.f, r2 = 0.f, r3 = 0.f;
#pragma unroll
        for (int f = 0; f < 16; f++) {
            float4 vv = __ldg(&vel[f]);
            float av = a[f];
            r0 += av * vv.x; r1 += av * vv.y; r2 += av * vv.z; r3 += av * vv.w;
        }
        g_le[l][pos] = make_float4(r0, r1, r2, r3);
    }
}

// ---------------- GEMM: C[n,128] = A[n,K] @ W[K,128] ----------------
// 128x128 block tile, 256 threads, 8x8 per thread, packed f32x2 FMAs.
__global__ void __launch_bounds__(256, 2) k_gemm(const float* __restrict__ A,
                                                 const float* __restrict__ W,
                                                 float* __restrict__ C, int n, int K) {
    __shared__ float As[32 * 132];   // [k][row]
    __shared__ float Bs[32 * 128];   // [k][col]
    int tid = threadIdx.x;
    int row0 = blockIdx.x * 128;
    int tx = tid & 15, ty = tid >> 4;
    int c0 = tx * 8;
    int r0 = ty * 8;

    ull acc[4][8];
#pragma unroll
    for (int p = 0; p < 4; p++)
#pragma unroll
        for (int j = 0; j < 8; j++) acc[p][j] = 0ull;

    for (int k0 = 0; k0 < K; k0 += 32) {
        int kk = tid & 31, rb = tid >> 5;
#pragma unroll
        for (int j = 0; j < 16; j++) {
            int r = rb + j * 8;
            int gr = row0 + r;
            float v = (gr < n) ? A[(size_t)gr * K + k0 + kk] : 0.f;
            As[kk * 132 + r] = v;
        }
        int nn = tid & 127;
#pragma unroll
        for (int j = 0; j < 16; j++) {
            int k2 = (tid >> 7) + j * 2;
            Bs[k2 * 128 + nn] = W[(size_t)(k0 + k2) * 128 + nn];
        }
        __syncthreads();
#pragma unroll
        for (int k = 0; k < 32; k++) {
            const ull* ap = (const ull*)&As[k * 132 + r0];
            ull av0 = ap[0], av1 = ap[1], av2 = ap[2], av3 = ap[3];
            float4 b0 = *(const float4*)&Bs[k * 128 + c0];
            float4 b1 = *(const float4*)&Bs[k * 128 + c0 + 4];
            ull bb0 = pk2(b0.x, b0.x), bb1 = pk2(b0.y, b0.y);
            ull bb2 = pk2(b0.z, b0.z), bb3 = pk2(b0.w, b0.w);
            ull bb4 = pk2(b1.x, b1.x), bb5 = pk2(b1.y, b1.y);
            ull bb6 = pk2(b1.z, b1.z), bb7 = pk2(b1.w, b1.w);
#pragma unroll
            for (int p = 0; p < 4; p++) {
                ull av = (p == 0) ? av0 : (p == 1) ? av1 : (p == 2) ? av2 : av3;
                fma2(acc[p][0], av, bb0);
                fma2(acc[p][1], av, bb1);
                fma2(acc[p][2], av, bb2);
                fma2(acc[p][3], av, bb3);
                fma2(acc[p][4], av, bb4);
                fma2(acc[p][5], av, bb5);
                fma2(acc[p][6], av, bb6);
                fma2(acc[p][7], av, bb7);
            }
        }
        __syncthreads();
    }
#pragma unroll
    for (int p = 0; p < 4; p++) {
        int r = row0 + r0 + 2 * p;
        if (r < n) {
            float4 v0 = make_float4(lo2(acc[p][0]), lo2(acc[p][1]), lo2(acc[p][2]), lo2(acc[p][3]));
            float4 v1 = make_float4(lo2(acc[p][4]), lo2(acc[p][5]), lo2(acc[p][6]), lo2(acc[p][7]));
            *(float4*)&C[(size_t)r * 128 + c0] = v0;
            *(float4*)&C[(size_t)r * 128 + c0 + 4] = v1;
        }
        if (r + 1 < n) {
            float4 v0 = make_float4(hi2(acc[p][0]), hi2(acc[p][1]), hi2(acc[p][2]), hi2(acc[p][3]));
            float4 v1 = make_float4(hi2(acc[p][4]), hi2(acc[p][5]), hi2(acc[p][6]), hi2(acc[p][7]));
            *(float4*)&C[(size_t)(r + 1) * 128 + c0] = v0;
            *(float4*)&C[(size_t)(r + 1) * 128 + c0 + 4] = v1;
        }
    }
}

// ---------------- per-node attention scalars ----------------
__global__ void k_lsld(const float* __restrict__ h, const float* __restrict__ aS,
                       const float* __restrict__ aD, int n) {
    int w = (blockIdx.x * blockDim.x + threadIdx.x) >> 5;
    int lane = threadIdx.x & 31;
    if (w >= n) return;
    float s[4], d[4];
#pragma unroll
    for (int hh = 0; hh < 4; hh++) {
        float v = h[(size_t)w * 128 + hh * 32 + lane];
        s[hh] = v * aS[hh * 32 + lane];
        d[hh] = v * aD[hh * 32 + lane];
    }
#pragma unroll
    for (int off = 16; off > 0; off >>= 1) {
#pragma unroll
        for (int hh = 0; hh < 4; hh++) {
            s[hh] += __shfl_xor_sync(0xffffffffu, s[hh], off);
            d[hh] += __shfl_xor_sync(0xffffffffu, d[hh], off);
        }
    }
    if (lane == 0) {
        g_ls[w] = make_float4(s[0], s[1], s[2], s[3]);
        g_ld[w] = make_float4(d[0], d[1], d[2], d[3]);
    }
}

// ---------------- single-pass segment softmax + weighted gather ----------------
// softmax is shift-invariant: skip max subtraction entirely (logits are O(10),
// exp cannot overflow fp32). alpha = exp(l)/sum exp(l) identical to reference.
template <bool ELU>
__global__ void __launch_bounds__(256) k_agg(const float* __restrict__ h,
                                             const float* __restrict__ bias,
                                             float* __restrict__ out, int n, int layer) {
    int w = (blockIdx.x * blockDim.x + threadIdx.x) >> 5;
    int lane = threadIdx.x & 31;
    if (w >= n) return;
    int beg = g_rowptr[w], end = g_rowptr[w + 1];
    float4 ldv = g_ld[w];
    float4 lsv = g_ls[w];
    float4 lself = *(const float4*)&g_leself[layer * 4];
    const float4* le = g_le[layer];

    // self-loop term
    float ex0 = __expf(lrelu(lsv.x + ldv.x + lself.x));
    float ex1 = __expf(lrelu(lsv.y + ldv.y + lself.y));
    float ex2 = __expf(lrelu(lsv.z + ldv.z + lself.z));
    float ex3 = __expf(lrelu(lsv.w + ldv.w + lself.w));
    float den0 = ex0, den1 = ex1, den2 = ex2, den3 = ex3;
    const float* hw = h + (size_t)w * 128 + lane;
    float acc0 = ex0 * hw[0];
    float acc1 = ex1 * hw[32];
    float acc2 = ex2 * hw[64];
    float acc3 = ex3 * hw[96];

    for (int i = beg; i < end; i++) {
        int s = __ldg(&g_srcs[i]);           // warp-broadcast
        float4 l4 = __ldg(&g_ls[s]);         // warp-broadcast
        float4 e4 = __ldg(&le[i]);           // warp-broadcast
        float t0 = __expf(lrelu(l4.x + ldv.x + e4.x));
        float t1 = __expf(lrelu(l4.y + ldv.y + e4.y));
        float t2 = __expf(lrelu(l4.z + ldv.z + e4.z));
        float t3 = __expf(lrelu(l4.w + ldv.w + e4.w));
        den0 += t0; den1 += t1; den2 += t2; den3 += t3;
        const float* hp = h + (size_t)s * 128 + lane;
        acc0 += t0 * hp[0];
        acc1 += t1 * hp[32];
        acc2 += t2 * hp[64];
        acc3 += t3 * hp[96];
    }

    float o0 = acc0 / (den0 + 1e-16f) + bias[lane];
    float o1 = acc1 / (den1 + 1e-16f) + bias[32 + lane];
    float o2 = acc2 / (den2 + 1e-16f) + bias[64 + lane];
    float o3 = acc3 / (den3 + 1e-16f) + bias[96 + lane];
    if (ELU) {
        o0 = o0 > 0.f ? o0 : (__expf(o0) - 1.f);
        o1 = o1 > 0.f ? o1 : (__expf(o1) - 1.f);
        o2 = o2 > 0.f ? o2 : (__expf(o2) - 1.f);
        o3 = o3 > 0.f ? o3 : (__expf(o3) - 1.f);
    }
    float* op = out + (size_t)w * 128 + lane;
    op[0] = o0; op[32] = o1; op[64] = o2; op[96] = o3;
}

// ---------------- heads ----------------
__global__ void __launch_bounds__(128) k_loc(const float* __restrict__ h,
                                             const float* __restrict__ Wl1, const float* __restrict__ bl1,
                                             const float* __restrict__ Wl2, const float* __restrict__ bl2,
                                             float* __restrict__ out, int n) {
    __shared__ float W1s[128 * 64];
    __shared__ float W2s[64];
    __shared__ float b1s[64];
    for (int i = threadIdx.x; i < 128 * 64; i += 128) W1s[i] = Wl1[i];
    if (threadIdx.x < 64) { W2s[threadIdx.x] = Wl2[threadIdx.x]; b1s[threadIdx.x] = bl1[threadIdx.x]; }
    __syncthreads();
    int nd = blockIdx.x * 128 + threadIdx.x;
    if (nd >= n) return;
    float t[64];
#pragma unroll
    for (int j = 0; j < 64; j++) t[j] = b1s[j];
    const float* hr = h + (size_t)nd * 128;
    for (int c = 0; c < 128; c++) {
        float hv = hr[c];
#pragma unroll
        for (int j = 0; j < 64; j++) t[j] += hv * W1s[c * 64 + j];
    }
    float o = bl2[0];
#pragma unroll
    for (int j = 0; j < 64; j++) o += fmaxf(t[j], 0.f) * W2s[j];
    out[640 + nd] = o;
}

__global__ void k_pool(const float* __restrict__ h, const int* __restrict__ batch, int n) {
    int base = blockIdx.x * 1024;
    int tid = threadIdx.x;
    int endr = min(base + 1024, n);
    float acc = 0.f; int cur = -1; int cnt = 0;
    for (int r = base; r < endr; r++) {
        int g = batch[r];
        if (g != cur) {
            if (cur >= 0) {
                atomicAdd(&g_gemb[cur * 128 + tid], acc);
                if (tid == 0) atomicAdd(&g_gcnt[cur], (float)cnt);
            }
            acc = 0.f; cnt = 0; cur = g;
        }
        acc += h[(size_t)r * 128 + tid];
        cnt++;
    }
    if (cur >= 0) {
        atomicAdd(&g_gemb[cur * 128 + tid], acc);
        if (tid == 0) atomicAdd(&g_gcnt[cur], (float)cnt);
    }
}

__global__ void __launch_bounds__(128) k_class(const float* __restrict__ Wc1, const float* __restrict__ bc1,
                                               const float* __restrict__ Wc2, const float* __restrict__ bc2,
                                               float* __restrict__ out) {
    __shared__ float e[128];
    __shared__ float t[128];
    int g = blockIdx.x, tid = threadIdx.x;
    float cnt = fmaxf(g_gcnt[g], 1.f);
    e[tid] = g_gemb[g * 128 + tid] / cnt;
    __syncthreads();
    float s = bc1[tid];
    for (int c = 0; c < 128; c++) s += e[c] * Wc1[c * 128 + tid];
    t[tid] = fmaxf(s, 0.f);
    __syncthreads();
    if (tid < NCLS) {
        float o = bc2[tid];
        for (int c = 0; c < 128; c++) o += t[c] * Wc2[c * NCLS + tid];
        out[g * NCLS + tid] = o;
    }
}

// ---------------- launch ----------------
extern "C" void kernel_launch(void* const* d_in, const int* in_sizes, int n_in,
                              void* d_out, int out_size) {
    const float* x       = (const float*)d_in[0];
    const int*   ei      = (const int*)d_in[1];
    const float* ea      = (const float*)d_in[2];
    const int*   batch   = (const int*)d_in[3];
    const float* W[3], *aS[3], *aD[3], *We[3], *aE[3], *b[3];
    int p = 4;
    for (int l = 0; l < 3; l++) {
        W[l]  = (const float*)d_in[p++];
        aS[l] = (const float*)d_in[p++];
        aD[l] = (const float*)d_in[p++];
        We[l] = (const float*)d_in[p++];
        aE[l] = (const float*)d_in[p++];
        b[l]  = (const float*)d_in[p++];
    }
    const float* Wc1 = (const float*)d_in[22];
    const float* bc1 = (const float*)d_in[23];
    const float* Wc2 = (const float*)d_in[24];
    const float* bc2 = (const float*)d_in[25];
    const float* Wl1 = (const float*)d_in[26];
    const float* bl1 = (const float*)d_in[27];
    const float* Wl2 = (const float*)d_in[28];
    const float* bl2 = (const float*)d_in[29];

    int n = in_sizes[0] / 64;
    int E = in_sizes[1] / 2;
    const int* src = ei;
    const int* dst = ei + E;
    float* out = (float*)d_out;

    void *p_h = nullptr, *p_act = nullptr;
    cudaGetSymbolAddress(&p_h, g_h);
    cudaGetSymbolAddress(&p_act, g_act);
    float* hbuf = (float*)p_h;
    float* actbuf = (float*)p_act;

    int nch = (n + 1023) / 1024;

    k_zero<<<(n + 255) / 256, 256>>>(n);
    k_hist<<<(E + 255) / 256, 256>>>(dst, E);
    k_scanA<<<nch, 256>>>(n);
    k_scanB<<<1, 32>>>(nch, n);
    k_scanC<<<nch, 256>>>(n);
    k_easum<<<256, 256>>>((const float4*)ea, E);
    k_ve<<<1, 256>>>(We[0], aE[0], We[1], aE[1], We[2], aE[2], E);
    k_scatter<<<(E + 255) / 256, 256>>>(src, dst, (const float4*)ea, E);

    int aggBlocks = (n * 32 + 255) / 256;
    const float* gin = x;
    int K = 64;
    for (int l = 0; l < 3; l++) {
        k_gemm<<<(n + 127) / 128, 256>>>(gin, W[l], hbuf, n, K);
        k_lsld<<<aggBlocks, 256>>>(hbuf, aS[l], aD[l], n);
        if (l < 2)
            k_agg<true><<<aggBlocks, 256>>>(hbuf, b[l], actbuf, n, l);
        else
            k_agg<false><<<aggBlocks, 256>>>(hbuf, b[l], actbuf, n, l);
        gin = actbuf;
        K = 128;
    }

    k_loc<<<(n + 127) / 128, 128>>>(actbuf, Wl1, bl1, Wl2, bl2, out, n);
    k_pool<<<nch, 128>>>(actbuf, batch, n);
    k_class<<<NGRP, 128>>>(Wc1, bc1, Wc2, bc2, out);
}

// round 3
// speedup vs baseline: 1.1004x; 1.1004x over previous
#include <cuda_runtime.h>
#include <math.h>

#define NMAX 100000
#define EMAX 1600000
#define HCD 128
#define NGRP 64
#define NCLS 10

typedef unsigned long long ull;

// ---------------- static device scratch ----------------
__device__ float  g_h[(size_t)NMAX * HCD];
__device__ float  g_act[(size_t)NMAX * HCD];
__device__ int    g_srcs[EMAX];
__device__ float4 g_le[3][EMAX];
__device__ float4 g_ex[EMAX];
__device__ float4 g_den[NMAX];
__device__ int    g_cnt[NMAX];
__device__ int    g_rowptr[NMAX + 1];
__device__ int    g_woff[NMAX];
__device__ int    g_bsum[1024];
__device__ int    g_boff[1024];
__device__ float4 g_ls[NMAX];
__device__ float4 g_ld[NMAX];
__device__ float  g_ve[3 * 16 * 4];
__device__ float  g_leself[12];
__device__ float  g_easum[16];
__device__ float  g_gemb[NGRP * HCD];
__device__ float  g_gcnt[NGRP];

// ---------------- helpers ----------------
__device__ __forceinline__ float lrelu(float x) { return x > 0.f ? x : 0.2f * x; }

__device__ __forceinline__ ull pk2(float x, float y) {
    ull r;
    asm("mov.b64 %0, {%1,%2};" : "=l"(r) : "r"(__float_as_uint(x)), "r"(__float_as_uint(y)));
    return r;
}
__device__ __forceinline__ void fma2(ull& d, ull a, ull b) {
    asm("fma.rn.f32x2 %0, %1, %2, %0;" : "+l"(d) : "l"(a), "l"(b));
}
__device__ __forceinline__ float lo2(ull v) { return __uint_as_float((unsigned)(v & 0xffffffffull)); }
__device__ __forceinline__ float hi2(ull v) { return __uint_as_float((unsigned)(v >> 32)); }

// ---------------- init / preprocessing ----------------
__global__ void k_zero(int n) {
    int i = blockIdx.x * blockDim.x + threadIdx.x;
    if (i < n) g_cnt[i] = 0;
    if (i < 16) g_easum[i] = 0.f;
    if (i < NGRP * HCD) g_gemb[i] = 0.f;
    if (i < NGRP) g_gcnt[i] = 0.f;
}

__global__ void k_hist(const int* __restrict__ dst, int E) {
    int e = blockIdx.x * blockDim.x + threadIdx.x;
    if (e < E) atomicAdd(&g_cnt[dst[e]], 1);
}

__global__ void k_scanA(int n) {
    __shared__ int sh[256];
    int base = blockIdx.x * 1024;
    int s = 0;
    for (int i = threadIdx.x; i < 1024; i += 256) {
        int idx = base + i;
        if (idx < n) s += g_cnt[idx];
    }
    sh[threadIdx.x] = s; __syncthreads();
    for (int d = 128; d > 0; d >>= 1) {
        if (threadIdx.x < d) sh[threadIdx.x] += sh[threadIdx.x + d];
        __syncthreads();
    }
    if (threadIdx.x == 0) g_bsum[blockIdx.x] = sh[0];
}

__global__ void k_scanB(int nchunks, int n) {
    if (threadIdx.x == 0) {
        int run = 0;
        for (int b = 0; b < nchunks; b++) { g_boff[b] = run; run += g_bsum[b]; }
        g_rowptr[n] = run;
    }
}

__global__ void k_scanC(int n) {
    __shared__ int sh[256];
    int base = blockIdx.x * 1024 + threadIdx.x * 4;
    int v[4];
#pragma unroll
    for (int j = 0; j < 4; j++) { int idx = base + j; v[j] = (idx < n) ? g_cnt[idx] : 0; }
    int s = v[0] + v[1] + v[2] + v[3];
    sh[threadIdx.x] = s; __syncthreads();
    for (int d = 1; d < 256; d <<= 1) {
        int add = (threadIdx.x >= (unsigned)d) ? sh[threadIdx.x - d] : 0;
        __syncthreads();
        sh[threadIdx.x] += add;
        __syncthreads();
    }
    int off = g_boff[blockIdx.x] + sh[threadIdx.x] - s;
#pragma unroll
    for (int j = 0; j < 4; j++) {
        int idx = base + j;
        if (idx < n) { g_rowptr[idx] = off; g_woff[idx] = off; off += v[j]; }
    }
}

__global__ void k_easum(const float4* __restrict__ ea4, int E) {
    float s[16];
#pragma unroll
    for (int f = 0; f < 16; f++) s[f] = 0.f;
    for (int e = blockIdx.x * blockDim.x + threadIdx.x; e < E; e += gridDim.x * blockDim.x) {
#pragma unroll
        for (int q = 0; q < 4; q++) {
            float4 v = ea4[(size_t)e * 4 + q];
            s[q * 4 + 0] += v.x; s[q * 4 + 1] += v.y; s[q * 4 + 2] += v.z; s[q * 4 + 3] += v.w;
        }
    }
    __shared__ float sm[16];
    if (threadIdx.x < 16) sm[threadIdx.x] = 0.f;
    __syncthreads();
#pragma unroll
    for (int f = 0; f < 16; f++) atomicAdd(&sm[f], s[f]);
    __syncthreads();
    if (threadIdx.x < 16) atomicAdd(&g_easum[threadIdx.x], sm[threadIdx.x]);
}

__global__ void k_ve(const float* We1, const float* aE1,
                     const float* We2, const float* aE2,
                     const float* We3, const float* aE3, int E) {
    int idx = threadIdx.x;
    const float* Wes[3] = { We1, We2, We3 };
    const float* aEs[3] = { aE1, aE2, aE3 };
    if (idx < 192) {
        int l = idx >> 6, f = (idx >> 2) & 15, h = idx & 3;
        const float* We = Wes[l]; const float* aE = aEs[l];
        float s = 0.f;
        for (int c = 0; c < 32; c++) s += We[f * 128 + h * 32 + c] * aE[h * 32 + c];
        g_ve[l * 64 + f * 4 + h] = s;
    }
    __syncthreads();
    if (idx < 12) {
        int l = idx >> 2, h = idx & 3;
        float inv = 1.f / (float)E;
        float s = 0.f;
        for (int f = 0; f < 16; f++) s += g_easum[f] * inv * g_ve[l * 64 + f * 4 + h];
        g_leself[l * 4 + h] = s;
    }
}

__global__ void k_scatter(const int* __restrict__ src, const int* __restrict__ dst,
                          const float4* __restrict__ ea4, int E) {
    int e = blockIdx.x * blockDim.x + threadIdx.x;
    if (e >= E) return;
    int d = dst[e];
    int pos = atomicAdd(&g_woff[d], 1);
    g_srcs[pos] = src[e];
    float a[16];
#pragma unroll
    for (int q = 0; q < 4; q++) {
        float4 v = ea4[(size_t)e * 4 + q];
        a[q * 4 + 0] = v.x; a[q * 4 + 1] = v.y; a[q * 4 + 2] = v.z; a[q * 4 + 3] = v.w;
    }
#pragma unroll
    for (int l = 0; l < 3; l++) {
        const float4* vel = (const float4*)&g_ve[l * 64];
        float r0 = 0.f, r1 = 0.f, r2 = 0.f, r3 = 0.f;
#pragma unroll
        for (int f = 0; f < 16; f++) {
            float4 vv = __ldg(&vel[f]);
            float av = a[f];
            r0 += av * vv.x; r1 += av * vv.y; r2 += av * vv.z; r3 += av * vv.w;
        }
        g_le[l][pos] = make_float4(r0, r1, r2, r3);
    }
}

// ---------------- GEMM + fused ls/ld: C[n,128]=A[n,K]@W[K,128] ----------------
// 128x128 tile, 256 threads, 8x8 per thread (row pairs packed in f32x2).
// NO min-blocks clause: ~170 regs, no spill.
__global__ void __launch_bounds__(256) k_gemm(const float* __restrict__ A,
                                              const float* __restrict__ W,
                                              float* __restrict__ C,
                                              const float* __restrict__ aS,
                                              const float* __restrict__ aD,
                                              int n, int K) {
    __shared__ float As[32 * 132];   // [k][row]
    __shared__ float Bs[32 * 128];   // [k][col]
    __shared__ float red[128 * 8];   // per-row: ls[4], ld[4]
    int tid = threadIdx.x;
    int row0 = blockIdx.x * 128;
    int tx = tid & 15, ty = tid >> 4;
    int c0 = tx * 8;
    int r0 = ty * 8;

    for (int i = tid; i < 1024; i += 256) red[i] = 0.f;

    ull acc[4][8];
#pragma unroll
    for (int p = 0; p < 4; p++)
#pragma unroll
        for (int j = 0; j < 8; j++) acc[p][j] = 0ull;

    for (int k0 = 0; k0 < K; k0 += 32) {
        int kk = tid & 31, rb = tid >> 5;
#pragma unroll
        for (int j = 0; j < 16; j++) {
            int r = rb + j * 8;
            int gr = row0 + r;
            float v = (gr < n) ? A[(size_t)gr * K + k0 + kk] : 0.f;
            As[kk * 132 + r] = v;
        }
        int nn = tid & 127;
#pragma unroll
        for (int j = 0; j < 16; j++) {
            int k2 = (tid >> 7) + j * 2;
            Bs[k2 * 128 + nn] = W[(size_t)(k0 + k2) * 128 + nn];
        }
        __syncthreads();
#pragma unroll
        for (int k = 0; k < 32; k++) {
            const ull* ap = (const ull*)&As[k * 132 + r0];
            ull av0 = ap[0], av1 = ap[1], av2 = ap[2], av3 = ap[3];
            float4 b0 = *(const float4*)&Bs[k * 128 + c0];
            float4 b1 = *(const float4*)&Bs[k * 128 + c0 + 4];
            ull bb0 = pk2(b0.x, b0.x), bb1 = pk2(b0.y, b0.y);
            ull bb2 = pk2(b0.z, b0.z), bb3 = pk2(b0.w, b0.w);
            ull bb4 = pk2(b1.x, b1.x), bb5 = pk2(b1.y, b1.y);
            ull bb6 = pk2(b1.z, b1.z), bb7 = pk2(b1.w, b1.w);
#pragma unroll
            for (int p = 0; p < 4; p++) {
                ull av = (p == 0) ? av0 : (p == 1) ? av1 : (p == 2) ? av2 : av3;
                fma2(acc[p][0], av, bb0);
                fma2(acc[p][1], av, bb1);
                fma2(acc[p][2], av, bb2);
                fma2(acc[p][3], av, bb3);
                fma2(acc[p][4], av, bb4);
                fma2(acc[p][5], av, bb5);
                fma2(acc[p][6], av, bb6);
                fma2(acc[p][7], av, bb7);
            }
        }
        __syncthreads();
    }

    // fused ls/ld partials: 8 cols of this thread lie in a single head
    int hd = c0 >> 5;
    float as8[8], ad8[8];
#pragma unroll
    for (int j = 0; j < 8; j++) { as8[j] = aS[c0 + j]; ad8[j] = aD[c0 + j]; }
#pragma unroll
    for (int p = 0; p < 4; p++) {
        float sSlo = 0.f, sShi = 0.f, sDlo = 0.f, sDhi = 0.f;
#pragma unroll
        for (int j = 0; j < 8; j++) {
            float lo = lo2(acc[p][j]), hi = hi2(acc[p][j]);
            sSlo += lo * as8[j]; sShi += hi * as8[j];
            sDlo += lo * ad8[j]; sDhi += hi * ad8[j];
        }
        int r = r0 + 2 * p;
        atomicAdd(&red[r * 8 + hd], sSlo);
        atomicAdd(&red[r * 8 + 4 + hd], sDlo);
        atomicAdd(&red[(r + 1) * 8 + hd], sShi);
        atomicAdd(&red[(r + 1) * 8 + 4 + hd], sDhi);
    }

    // store C
#pragma unroll
    for (int p = 0; p < 4; p++) {
        int r = row0 + r0 + 2 * p;
        if (r < n) {
            float4 v0 = make_float4(lo2(acc[p][0]), lo2(acc[p][1]), lo2(acc[p][2]), lo2(acc[p][3]));
            float4 v1 = make_float4(lo2(acc[p][4]), lo2(acc[p][5]), lo2(acc[p][6]), lo2(acc[p][7]));
            *(float4*)&C[(size_t)r * 128 + c0] = v0;
            *(float4*)&C[(size_t)r * 128 + c0 + 4] = v1;
        }
        if (r + 1 < n) {
            float4 v0 = make_float4(hi2(acc[p][0]), hi2(acc[p][1]), hi2(acc[p][2]), hi2(acc[p][3]));
            float4 v1 = make_float4(hi2(acc[p][4]), hi2(acc[p][5]), hi2(acc[p][6]), hi2(acc[p][7]));
            *(float4*)&C[(size_t)(r + 1) * 128 + c0] = v0;
            *(float4*)&C[(size_t)(r + 1) * 128 + c0 + 4] = v1;
        }
    }

    __syncthreads();
    {
        int r = tid >> 1;
        int which = tid & 1;
        int gr = row0 + r;
        if (gr < n) {
            float4 v = *(const float4*)&red[r * 8 + which * 4];
            if (which == 0) g_ls[gr] = v; else g_ld[gr] = v;
        }
    }
}

// ---------------- pass B: lane-parallel exp + den (no max pass needed) ----------------
__global__ void __launch_bounds__(256) k_exp(int n, int layer) {
    int w = (blockIdx.x * blockDim.x + threadIdx.x) >> 5;
    int lane = threadIdx.x & 31;
    if (w >= n) return;
    int beg = g_rowptr[w], end = g_rowptr[w + 1];
    float4 ldv = g_ld[w];
    const float4* le = g_le[layer];
    float d0 = 0.f, d1 = 0.f, d2 = 0.f, d3 = 0.f;
    for (int i = beg + lane; i < end; i += 32) {
        int s = __ldg(&g_srcs[i]);
        float4 l4 = __ldg(&g_ls[s]);
        float4 e4 = __ldg(&le[i]);
        float4 t;
        t.x = __expf(lrelu(l4.x + ldv.x + e4.x));
        t.y = __expf(lrelu(l4.y + ldv.y + e4.y));
        t.z = __expf(lrelu(l4.z + ldv.z + e4.z));
        t.w = __expf(lrelu(l4.w + ldv.w + e4.w));
        g_ex[i] = t;
        d0 += t.x; d1 += t.y; d2 += t.z; d3 += t.w;
    }
#pragma unroll
    for (int off = 16; off > 0; off >>= 1) {
        d0 += __shfl_xor_sync(0xffffffffu, d0, off);
        d1 += __shfl_xor_sync(0xffffffffu, d1, off);
        d2 += __shfl_xor_sync(0xffffffffu, d2, off);
        d3 += __shfl_xor_sync(0xffffffffu, d3, off);
    }
    if (lane == 0) g_den[w] = make_float4(d0, d1, d2, d3);
}

// ---------------- pass C: weighted gather ----------------
template <bool ELU>
__global__ void __launch_bounds__(256) k_agg(const float* __restrict__ h,
                                             const float* __restrict__ bias,
                                             float* __restrict__ out, int n, int layer) {
    int w = (blockIdx.x * blockDim.x + threadIdx.x) >> 5;
    int lane = threadIdx.x & 31;
    if (w >= n) return;
    int beg = g_rowptr[w], end = g_rowptr[w + 1];
    float4 ldv = g_ld[w];
    float4 lsv = g_ls[w];
    float4 lself = *(const float4*)&g_leself[layer * 4];
    float4 dv = g_den[w];

    float ex0 = __expf(lrelu(lsv.x + ldv.x + lself.x));
    float ex1 = __expf(lrelu(lsv.y + ldv.y + lself.y));
    float ex2 = __expf(lrelu(lsv.z + ldv.z + lself.z));
    float ex3 = __expf(lrelu(lsv.w + ldv.w + lself.w));
    float den0 = dv.x + ex0 + 1e-16f;
    float den1 = dv.y + ex1 + 1e-16f;
    float den2 = dv.z + ex2 + 1e-16f;
    float den3 = dv.w + ex3 + 1e-16f;

    const float* hw = h + (size_t)w * 128 + lane;
    float acc0 = ex0 * hw[0];
    float acc1 = ex1 * hw[32];
    float acc2 = ex2 * hw[64];
    float acc3 = ex3 * hw[96];

#pragma unroll 2
    for (int i = beg; i < end; i++) {
        int s = __ldg(&g_srcs[i]);
        float4 e = __ldg(&g_ex[i]);
        const float* hp = h + (size_t)s * 128 + lane;
        acc0 += e.x * hp[0];
        acc1 += e.y * hp[32];
        acc2 += e.z * hp[64];
        acc3 += e.w * hp[96];
    }

    float o0 = acc0 / den0 + bias[lane];
    float o1 = acc1 / den1 + bias[32 + lane];
    float o2 = acc2 / den2 + bias[64 + lane];
    float o3 = acc3 / den3 + bias[96 + lane];
    if (ELU) {
        o0 = o0 > 0.f ? o0 : (__expf(o0) - 1.f);
        o1 = o1 > 0.f ? o1 : (__expf(o1) - 1.f);
        o2 = o2 > 0.f ? o2 : (__expf(o2) - 1.f);
        o3 = o3 > 0.f ? o3 : (__expf(o3) - 1.f);
    }
    float* op = out + (size_t)w * 128 + lane;
    op[0] = o0; op[32] = o1; op[64] = o2; op[96] = o3;
}

// ---------------- heads ----------------
__global__ void __launch_bounds__(128) k_loc(const float* __restrict__ h,
                                             const float* __restrict__ Wl1, const float* __restrict__ bl1,
                                             const float* __restrict__ Wl2, const float* __restrict__ bl2,
                                             float* __restrict__ out, int n) {
    __shared__ float W1s[128 * 64];
    __shared__ float W2s[64];
    __shared__ float b1s[64];
    for (int i = threadIdx.x; i < 128 * 64; i += 128) W1s[i] = Wl1[i];
    if (threadIdx.x < 64) { W2s[threadIdx.x] = Wl2[threadIdx.x]; b1s[threadIdx.x] = bl1[threadIdx.x]; }
    __syncthreads();
    int nd = blockIdx.x * 128 + threadIdx.x;
    if (nd >= n) return;
    float t[64];
#pragma unroll
    for (int j = 0; j < 64; j++) t[j] = b1s[j];
    const float* hr = h + (size_t)nd * 128;
    for (int c = 0; c < 128; c++) {
        float hv = hr[c];
#pragma unroll
        for (int j = 0; j < 64; j++) t[j] += hv * W1s[c * 64 + j];
    }
    float o = bl2[0];
#pragma unroll
    for (int j = 0; j < 64; j++) o += fmaxf(t[j], 0.f) * W2s[j];
    out[640 + nd] = o;
}

__global__ void k_pool(const float* __restrict__ h, const int* __restrict__ batch, int n) {
    int base = blockIdx.x * 1024;
    int tid = threadIdx.x;
    int endr = min(base + 1024, n);
    float acc = 0.f; int cur = -1; int cnt = 0;
    for (int r = base; r < endr; r++) {
        int g = batch[r];
        if (g != cur) {
            if (cur >= 0) {
                atomicAdd(&g_gemb[cur * 128 + tid], acc);
                if (tid == 0) atomicAdd(&g_gcnt[cur], (float)cnt);
            }
            acc = 0.f; cnt = 0; cur = g;
        }
        acc += h[(size_t)r * 128 + tid];
        cnt++;
    }
    if (cur >= 0) {
        atomicAdd(&g_gemb[cur * 128 + tid], acc);
        if (tid == 0) atomicAdd(&g_gcnt[cur], (float)cnt);
    }
}

__global__ void __launch_bounds__(128) k_class(const float* __restrict__ Wc1, const float* __restrict__ bc1,
                                               const float* __restrict__ Wc2, const float* __restrict__ bc2,
                                               float* __restrict__ out) {
    __shared__ float e[128];
    __shared__ float t[128];
    int g = blockIdx.x, tid = threadIdx.x;
    float cnt = fmaxf(g_gcnt[g], 1.f);
    e[tid] = g_gemb[g * 128 + tid] / cnt;
    __syncthreads();
    float s = bc1[tid];
    for (int c = 0; c < 128; c++) s += e[c] * Wc1[c * 128 + tid];
    t[tid] = fmaxf(s, 0.f);
    __syncthreads();
    if (tid < NCLS) {
        float o = bc2[tid];
        for (int c = 0; c < 128; c++) o += t[c] * Wc2[c * NCLS + tid];
        out[g * NCLS + tid] = o;
    }
}

// ---------------- launch ----------------
extern "C" void kernel_launch(void* const* d_in, const int* in_sizes, int n_in,
                              void* d_out, int out_size) {
    const float* x       = (const float*)d_in[0];
    const int*   ei      = (const int*)d_in[1];
    const float* ea      = (const float*)d_in[2];
    const int*   batch   = (const int*)d_in[3];
    const float* W[3], *aS[3], *aD[3], *We[3], *aE[3], *b[3];
    int p = 4;
    for (int l = 0; l < 3; l++) {
        W[l]  = (const float*)d_in[p++];
        aS[l] = (const float*)d_in[p++];
        aD[l] = (const float*)d_in[p++];
        We[l] = (const float*)d_in[p++];
        aE[l] = (const float*)d_in[p++];
        b[l]  = (const float*)d_in[p++];
    }
    const float* Wc1 = (const float*)d_in[22];
    const float* bc1 = (const float*)d_in[23];
    const float* Wc2 = (const float*)d_in[24];
    const float* bc2 = (const float*)d_in[25];
    const float* Wl1 = (const float*)d_in[26];
    const float* bl1 = (const float*)d_in[27];
    const float* Wl2 = (const float*)d_in[28];
    const float* bl2 = (const float*)d_in[29];

    int n = in_sizes[0] / 64;
    int E = in_sizes[1] / 2;
    const int* src = ei;
    const int* dst = ei + E;
    float* out = (float*)d_out;

    void *p_h = nullptr, *p_act = nullptr;
    cudaGetSymbolAddress(&p_h, g_h);
    cudaGetSymbolAddress(&p_act, g_act);
    float* hbuf = (float*)p_h;
    float* actbuf = (float*)p_act;

    int nch = (n + 1023) / 1024;

    k_zero<<<(n + 255) / 256, 256>>>(n);
    // layer-1 GEMM depends only on x/W1 — launch before edge preprocessing
    k_gemm<<<(n + 127) / 128, 256>>>(x, W[0], hbuf, aS[0], aD[0], n, 64);

    k_hist<<<(E + 255) / 256, 256>>>(dst, E);
    k_scanA<<<nch, 256>>>(n);
    k_scanB<<<1, 32>>>(nch, n);
    k_scanC<<<nch, 256>>>(n);
    k_easum<<<256, 256>>>((const float4*)ea, E);
    k_ve<<<1, 256>>>(We[0], aE[0], We[1], aE[1], We[2], aE[2], E);
    k_scatter<<<(E + 255) / 256, 256>>>(src, dst, (const float4*)ea, E);

    int aggBlocks = (n * 32 + 255) / 256;
    for (int l = 0; l < 3; l++) {
        if (l > 0)
            k_gemm<<<(n + 127) / 128, 256>>>(actbuf, W[l], hbuf, aS[l], aD[l], n, 128);
        k_exp<<<aggBlocks, 256>>>(n, l);
        if (l < 2)
            k_agg<true><<<aggBlocks, 256>>>(hbuf, b[l], actbuf, n, l);
        else
            k_agg<false><<<aggBlocks, 256>>>(hbuf, b[l], actbuf, n, l);
    }

    k_loc<<<(n + 127) / 128, 128>>>(actbuf, Wl1, bl1, Wl2, bl2, out, n);
    k_pool<<<nch, 128>>>(actbuf, batch, n);
    k_class<<<NGRP, 128>>>(Wc1, bc1, Wc2, bc2, out);
}

// round 4
// speedup vs baseline: 1.1585x; 1.0527x over previous
#include <cuda_runtime.h>
#include <math.h>

#define NMAX 100000
#define EMAX 1600000
#define HCD 128
#define NGRP 64
#define NCLS 10

typedef unsigned long long ull;

// ---------------- static device scratch ----------------
__device__ float  g_h[(size_t)NMAX * HCD];
__device__ float  g_act[(size_t)NMAX * HCD];
__device__ int    g_srcs[EMAX];
__device__ float4 g_le[3][EMAX];
__device__ int    g_cnt[NMAX];
__device__ int    g_rowptr[NMAX + 1];
__device__ int    g_woff[NMAX];
__device__ int    g_bsum[1024];
__device__ int    g_boff[1024];
__device__ float4 g_ls[NMAX];
__device__ float4 g_ld[NMAX];
__device__ float  g_ve[3 * 16 * 4];
__device__ float  g_leself[12];
__device__ float  g_easum[16];
__device__ float  g_gemb[NGRP * HCD];
__device__ float  g_gcnt[NGRP];

// ---------------- helpers ----------------
__device__ __forceinline__ float lrelu(float x) { return x > 0.f ? x : 0.2f * x; }
__device__ __forceinline__ float pick4(float4 v, int hd) {
    return hd == 0 ? v.x : hd == 1 ? v.y : hd == 2 ? v.z : v.w;
}

__device__ __forceinline__ ull pk2(float x, float y) {
    ull r;
    asm("mov.b64 %0, {%1,%2};" : "=l"(r) : "r"(__float_as_uint(x)), "r"(__float_as_uint(y)));
    return r;
}
__device__ __forceinline__ void fma2(ull& d, ull a, ull b) {
    asm("fma.rn.f32x2 %0, %1, %2, %0;" : "+l"(d) : "l"(a), "l"(b));
}
__device__ __forceinline__ float lo2(ull v) { return __uint_as_float((unsigned)(v & 0xffffffffull)); }
__device__ __forceinline__ float hi2(ull v) { return __uint_as_float((unsigned)(v >> 32)); }

// ---------------- init / preprocessing ----------------
__global__ void k_zero(int n) {
    int i = blockIdx.x * blockDim.x + threadIdx.x;
    if (i < n) g_cnt[i] = 0;
    if (i < 16) g_easum[i] = 0.f;
    if (i < NGRP * HCD) g_gemb[i] = 0.f;
    if (i < NGRP) g_gcnt[i] = 0.f;
}

__global__ void k_hist(const int* __restrict__ dst, int E) {
    int e = blockIdx.x * blockDim.x + threadIdx.x;
    if (e < E) atomicAdd(&g_cnt[dst[e]], 1);
}

__global__ void k_scanA(int n) {
    __shared__ int sh[256];
    int base = blockIdx.x * 1024;
    int s = 0;
    for (int i = threadIdx.x; i < 1024; i += 256) {
        int idx = base + i;
        if (idx < n) s += g_cnt[idx];
    }
    sh[threadIdx.x] = s; __syncthreads();
    for (int d = 128; d > 0; d >>= 1) {
        if (threadIdx.x < d) sh[threadIdx.x] += sh[threadIdx.x + d];
        __syncthreads();
    }
    if (threadIdx.x == 0) g_bsum[blockIdx.x] = sh[0];
}

__global__ void k_scanB(int nchunks, int n) {
    if (threadIdx.x == 0) {
        int run = 0;
        for (int b = 0; b < nchunks; b++) { g_boff[b] = run; run += g_bsum[b]; }
        g_rowptr[n] = run;
    }
}

__global__ void k_scanC(int n) {
    __shared__ int sh[256];
    int base = blockIdx.x * 1024 + threadIdx.x * 4;
    int v[4];
#pragma unroll
    for (int j = 0; j < 4; j++) { int idx = base + j; v[j] = (idx < n) ? g_cnt[idx] : 0; }
    int s = v[0] + v[1] + v[2] + v[3];
    sh[threadIdx.x] = s; __syncthreads();
    for (int d = 1; d < 256; d <<= 1) {
        int add = (threadIdx.x >= (unsigned)d) ? sh[threadIdx.x - d] : 0;
        __syncthreads();
        sh[threadIdx.x] += add;
        __syncthreads();
    }
    int off = g_boff[blockIdx.x] + sh[threadIdx.x] - s;
#pragma unroll
    for (int j = 0; j < 4; j++) {
        int idx = base + j;
        if (idx < n) { g_rowptr[idx] = off; g_woff[idx] = off; off += v[j]; }
    }
}

__global__ void k_easum(const float4* __restrict__ ea4, int E) {
    float s[16];
#pragma unroll
    for (int f = 0; f < 16; f++) s[f] = 0.f;
    for (int e = blockIdx.x * blockDim.x + threadIdx.x; e < E; e += gridDim.x * blockDim.x) {
#pragma unroll
        for (int q = 0; q < 4; q++) {
            float4 v = ea4[(size_t)e * 4 + q];
            s[q * 4 + 0] += v.x; s[q * 4 + 1] += v.y; s[q * 4 + 2] += v.z; s[q * 4 + 3] += v.w;
        }
    }
    __shared__ float sm[16];
    if (threadIdx.x < 16) sm[threadIdx.x] = 0.f;
    __syncthreads();
#pragma unroll
    for (int f = 0; f < 16; f++) atomicAdd(&sm[f], s[f]);
    __syncthreads();
    if (threadIdx.x < 16) atomicAdd(&g_easum[threadIdx.x], sm[threadIdx.x]);
}

__global__ void k_ve(const float* We1, const float* aE1,
                     const float* We2, const float* aE2,
                     const float* We3, const float* aE3, int E) {
    int idx = threadIdx.x;
    const float* Wes[3] = { We1, We2, We3 };
    const float* aEs[3] = { aE1, aE2, aE3 };
    if (idx < 192) {
        int l = idx >> 6, f = (idx >> 2) & 15, h = idx & 3;
        const float* We = Wes[l]; const float* aE = aEs[l];
        float s = 0.f;
        for (int c = 0; c < 32; c++) s += We[f * 128 + h * 32 + c] * aE[h * 32 + c];
        g_ve[l * 64 + f * 4 + h] = s;
    }
    __syncthreads();
    if (idx < 12) {
        int l = idx >> 2, h = idx & 3;
        float inv = 1.f / (float)E;
        float s = 0.f;
        for (int f = 0; f < 16; f++) s += g_easum[f] * inv * g_ve[l * 64 + f * 4 + h];
        g_leself[l * 4 + h] = s;
    }
}

__global__ void k_scatter(const int* __restrict__ src, const int* __restrict__ dst,
                          const float4* __restrict__ ea4, int E) {
    int e = blockIdx.x * blockDim.x + threadIdx.x;
    if (e >= E) return;
    int d = dst[e];
    int pos = atomicAdd(&g_woff[d], 1);
    g_srcs[pos] = src[e];
    float a[16];
#pragma unroll
    for (int q = 0; q < 4; q++) {
        float4 v = ea4[(size_t)e * 4 + q];
        a[q * 4 + 0] = v.x; a[q * 4 + 1] = v.y; a[q * 4 + 2] = v.z; a[q * 4 + 3] = v.w;
    }
#pragma unroll
    for (int l = 0; l < 3; l++) {
        const float4* vel = (const float4*)&g_ve[l * 64];
        float r0 = 0.f, r1 = 0.f, r2 = 0.f, r3 = 0.f;
#pragma unroll
        for (int f = 0; f < 16; f++) {
            float4 vv = __ldg(&vel[f]);
            float av = a[f];
            r0 += av * vv.x; r1 += av * vv.y; r2 += av * vv.z; r3 += av * vv.w;
        }
        g_le[l][pos] = make_float4(r0, r1, r2, r3);
    }
}

// ---------------- GEMM + fused ls/ld: C[n,128]=A[n,K]@W[K,128] ----------------
// 64x128 tile, 256 threads, 8x4 per thread (row pairs in f32x2), ~3 CTAs/SM.
__global__ void __launch_bounds__(256) k_gemm(const float* __restrict__ A,
                                              const float* __restrict__ W,
                                              float* __restrict__ C,
                                              const float* __restrict__ aS,
                                              const float* __restrict__ aD,
                                              int n, int K) {
    __shared__ float As[32 * 66];   // [k][row]
    __shared__ float Bs[32 * 128];  // [k][col]
    __shared__ float red[64 * 8];   // per-row: ls[4], ld[4]
    int tid = threadIdx.x;
    int row0 = blockIdx.x * 64;
    int tx = tid & 31, ty = tid >> 5;
    int c0 = tx * 4;
    int r0 = ty * 8;

    for (int i = tid; i < 512; i += 256) red[i] = 0.f;

    ull acc[4][4];
#pragma unroll
    for (int p = 0; p < 4; p++)
#pragma unroll
        for (int j = 0; j < 4; j++) acc[p][j] = 0ull;

    for (int k0 = 0; k0 < K; k0 += 32) {
        int kk = tid & 31, rb = tid >> 5;
#pragma unroll
        for (int j = 0; j < 8; j++) {
            int r = rb + j * 8;
            int gr = row0 + r;
            float v = (gr < n) ? A[(size_t)gr * K + k0 + kk] : 0.f;
            As[kk * 66 + r] = v;
        }
        int nn = tid & 127;
#pragma unroll
        for (int j = 0; j < 16; j++) {
            int k2 = (tid >> 7) + j * 2;
            Bs[k2 * 128 + nn] = W[(size_t)(k0 + k2) * 128 + nn];
        }
        __syncthreads();
#pragma unroll
        for (int k = 0; k < 32; k++) {
            float4 bv = *(const float4*)&Bs[k * 128 + c0];
            ull bb0 = pk2(bv.x, bv.x);
            ull bb1 = pk2(bv.y, bv.y);
            ull bb2 = pk2(bv.z, bv.z);
            ull bb3 = pk2(bv.w, bv.w);
            const ull* a2 = (const ull*)&As[k * 66 + r0];
#pragma unroll
            for (int p = 0; p < 4; p++) {
                ull av = a2[p];
                fma2(acc[p][0], av, bb0);
                fma2(acc[p][1], av, bb1);
                fma2(acc[p][2], av, bb2);
                fma2(acc[p][3], av, bb3);
            }
        }
        __syncthreads();
    }

    // fused ls/ld partials: 4 cols of this thread lie in a single head
    int hd = tx >> 3;
    float as4[4], ad4[4];
#pragma unroll
    for (int j = 0; j < 4; j++) { as4[j] = aS[c0 + j]; ad4[j] = aD[c0 + j]; }
#pragma unroll
    for (int p = 0; p < 4; p++) {
        float sSlo = 0.f, sShi = 0.f, sDlo = 0.f, sDhi = 0.f;
#pragma unroll
        for (int j = 0; j < 4; j++) {
            float lo = lo2(acc[p][j]), hi = hi2(acc[p][j]);
            sSlo += lo * as4[j]; sShi += hi * as4[j];
            sDlo += lo * ad4[j]; sDhi += hi * ad4[j];
        }
        int r = r0 + 2 * p;
        atomicAdd(&red[r * 8 + hd], sSlo);
        atomicAdd(&red[r * 8 + 4 + hd], sDlo);
        atomicAdd(&red[(r + 1) * 8 + hd], sShi);
        atomicAdd(&red[(r + 1) * 8 + 4 + hd], sDhi);
    }

    // store C
#pragma unroll
    for (int p = 0; p < 4; p++) {
        int r = row0 + r0 + 2 * p;
        if (r < n) {
            float4 v = make_float4(lo2(acc[p][0]), lo2(acc[p][1]), lo2(acc[p][2]), lo2(acc[p][3]));
            *(float4*)&C[(size_t)r * 128 + c0] = v;
        }
        if (r + 1 < n) {
            float4 v = make_float4(hi2(acc[p][0]), hi2(acc[p][1]), hi2(acc[p][2]), hi2(acc[p][3]));
            *(float4*)&C[(size_t)(r + 1) * 128 + c0] = v;
        }
    }

    __syncthreads();
    if (tid < 128) {
        int r = tid >> 1;
        int which = tid & 1;
        int gr = row0 + r;
        if (gr < n) {
            float4 v = *(const float4*)&red[r * 8 + which * 4];
            if (which == 0) g_ls[gr] = v; else g_ld[gr] = v;
        }
    }
}

// ---------------- single-pass agg: chunked lane-parallel exp + smem-staged gather ----------------
template <bool ELU>
__global__ void __launch_bounds__(256) k_agg(const float* __restrict__ h,
                                             const float* __restrict__ bias,
                                             float* __restrict__ out, int n, int layer) {
    __shared__ int    sS[8][32];
    __shared__ float4 sT[8][32];
    int wib = threadIdx.x >> 5;
    int lane = threadIdx.x & 31;
    int w = (blockIdx.x * blockDim.x + threadIdx.x) >> 5;
    if (w >= n) return;
    int beg = g_rowptr[w], end = g_rowptr[w + 1];
    float4 ldv = g_ld[w];
    float4 lsv = g_ls[w];
    float4 lself = *(const float4*)&g_leself[layer * 4];
    const float4* le = g_le[layer];
    int hd = lane >> 3;   // head for channels lane*4..lane*4+3

    // self-loop term (same on all lanes)
    float4 exs;
    exs.x = __expf(lrelu(lsv.x + ldv.x + lself.x));
    exs.y = __expf(lrelu(lsv.y + ldv.y + lself.y));
    exs.z = __expf(lrelu(lsv.z + ldv.z + lself.z));
    exs.w = __expf(lrelu(lsv.w + ldv.w + lself.w));

    float4 hv = __ldg((const float4*)(h + (size_t)w * 128) + lane);
    float exmy = pick4(exs, hd);
    float4 acc = make_float4(exmy * hv.x, exmy * hv.y, exmy * hv.z, exmy * hv.w);
    float4 dpart = (lane == 0) ? exs : make_float4(0.f, 0.f, 0.f, 0.f);

    for (int base = beg; base < end; base += 32) {
        int m = end - base;
        if (m > 32) m = 32;
        int s = 0;
        float4 t = make_float4(0.f, 0.f, 0.f, 0.f);
        if (lane < m) {
            int i = base + lane;
            s = __ldg(&g_srcs[i]);
            float4 l4 = __ldg(&g_ls[s]);
            float4 e4 = __ldg(&le[i]);
            t.x = __expf(lrelu(l4.x + ldv.x + e4.x));
            t.y = __expf(lrelu(l4.y + ldv.y + e4.y));
            t.z = __expf(lrelu(l4.z + ldv.z + e4.z));
            t.w = __expf(lrelu(l4.w + ldv.w + e4.w));
        }
        dpart.x += t.x; dpart.y += t.y; dpart.z += t.z; dpart.w += t.w;
        sS[wib][lane] = s;
        sT[wib][lane] = t;
        __syncwarp();
#pragma unroll 4
        for (int j = 0; j < m; j++) {
            int sj = sS[wib][j];
            float tj = ((const float*)&sT[wib][j])[hd];
            float4 hj = __ldg((const float4*)(h + (size_t)sj * 128) + lane);
            acc.x += tj * hj.x;
            acc.y += tj * hj.y;
            acc.z += tj * hj.z;
            acc.w += tj * hj.w;
        }
        __syncwarp();
    }

#pragma unroll
    for (int off = 16; off > 0; off >>= 1) {
        dpart.x += __shfl_xor_sync(0xffffffffu, dpart.x, off);
        dpart.y += __shfl_xor_sync(0xffffffffu, dpart.y, off);
        dpart.z += __shfl_xor_sync(0xffffffffu, dpart.z, off);
        dpart.w += __shfl_xor_sync(0xffffffffu, dpart.w, off);
    }
    float den = pick4(dpart, hd) + 1e-16f;
    float inv = 1.f / den;
    float4 b4 = __ldg((const float4*)bias + lane);
    float4 o;
    o.x = acc.x * inv + b4.x;
    o.y = acc.y * inv + b4.y;
    o.z = acc.z * inv + b4.z;
    o.w = acc.w * inv + b4.w;
    if (ELU) {
        o.x = o.x > 0.f ? o.x : (__expf(o.x) - 1.f);
        o.y = o.y > 0.f ? o.y : (__expf(o.y) - 1.f);
        o.z = o.z > 0.f ? o.z : (__expf(o.z) - 1.f);
        o.w = o.w > 0.f ? o.w : (__expf(o.w) - 1.f);
    }
    *((float4*)(out + (size_t)w * 128) + lane) = o;
}

// ---------------- heads ----------------
__global__ void __launch_bounds__(128) k_loc(const float* __restrict__ h,
                                             const float* __restrict__ Wl1, const float* __restrict__ bl1,
                                             const float* __restrict__ Wl2, const float* __restrict__ bl2,
                                             float* __restrict__ out, int n) {
    __shared__ float W1s[128 * 64];
    __shared__ float W2s[64];
    __shared__ float b1s[64];
    for (int i = threadIdx.x; i < 128 * 64; i += 128) W1s[i] = Wl1[i];
    if (threadIdx.x < 64) { W2s[threadIdx.x] = Wl2[threadIdx.x]; b1s[threadIdx.x] = bl1[threadIdx.x]; }
    __syncthreads();
    int nd = blockIdx.x * 128 + threadIdx.x;
    if (nd >= n) return;
    float t[64];
#pragma unroll
    for (int j = 0; j < 64; j++) t[j] = b1s[j];
    const float* hr = h + (size_t)nd * 128;
    for (int c = 0; c < 128; c++) {
        float hv = hr[c];
#pragma unroll
        for (int j = 0; j < 64; j++) t[j] += hv * W1s[c * 64 + j];
    }
    float o = bl2[0];
#pragma unroll
    for (int j = 0; j < 64; j++) o += fmaxf(t[j], 0.f) * W2s[j];
    out[640 + nd] = o;
}

__global__ void k_pool(const float* __restrict__ h, const int* __restrict__ batch, int n) {
    int base = blockIdx.x * 1024;
    int tid = threadIdx.x;
    int endr = min(base + 1024, n);
    float acc = 0.f; int cur = -1; int cnt = 0;
    for (int r = base; r < endr; r++) {
        int g = batch[r];
        if (g != cur) {
            if (cur >= 0) {
                atomicAdd(&g_gemb[cur * 128 + tid], acc);
                if (tid == 0) atomicAdd(&g_gcnt[cur], (float)cnt);
            }
            acc = 0.f; cnt = 0; cur = g;
        }
        acc += h[(size_t)r * 128 + tid];
        cnt++;
    }
    if (cur >= 0) {
        atomicAdd(&g_gemb[cur * 128 + tid], acc);
        if (tid == 0) atomicAdd(&g_gcnt[cur], (float)cnt);
    }
}

__global__ void __launch_bounds__(128) k_class(const float* __restrict__ Wc1, const float* __restrict__ bc1,
                                               const float* __restrict__ Wc2, const float* __restrict__ bc2,
                                               float* __restrict__ out) {
    __shared__ float e[128];
    __shared__ float t[128];
    int g = blockIdx.x, tid = threadIdx.x;
    float cnt = fmaxf(g_gcnt[g], 1.f);
    e[tid] = g_gemb[g * 128 + tid] / cnt;
    __syncthreads();
    float s = bc1[tid];
    for (int c = 0; c < 128; c++) s += e[c] * Wc1[c * 128 + tid];
    t[tid] = fmaxf(s, 0.f);
    __syncthreads();
    if (tid < NCLS) {
        float o = bc2[tid];
        for (int c = 0; c < 128; c++) o += t[c] * Wc2[c * NCLS + tid];
        out[g * NCLS + tid] = o;
    }
}

// ---------------- launch ----------------
extern "C" void kernel_launch(void* const* d_in, const int* in_sizes, int n_in,
                              void* d_out, int out_size) {
    const float* x       = (const float*)d_in[0];
    const int*   ei      = (const int*)d_in[1];
    const float* ea      = (const float*)d_in[2];
    const int*   batch   = (const int*)d_in[3];
    const float* W[3], *aS[3], *aD[3], *We[3], *aE[3], *b[3];
    int p = 4;
    for (int l = 0; l < 3; l++) {
        W[l]  = (const float*)d_in[p++];
        aS[l] = (const float*)d_in[p++];
        aD[l] = (const float*)d_in[p++];
        We[l] = (const float*)d_in[p++];
        aE[l] = (const float*)d_in[p++];
        b[l]  = (const float*)d_in[p++];
    }
    const float* Wc1 = (const float*)d_in[22];
    const float* bc1 = (const float*)d_in[23];
    const float* Wc2 = (const float*)d_in[24];
    const float* bc2 = (const float*)d_in[25];
    const float* Wl1 = (const float*)d_in[26];
    const float* bl1 = (const float*)d_in[27];
    const float* Wl2 = (const float*)d_in[28];
    const float* bl2 = (const float*)d_in[29];

    int n = in_sizes[0] / 64;
    int E = in_sizes[1] / 2;
    const int* src = ei;
    const int* dst = ei + E;
    float* out = (float*)d_out;

    void *p_h = nullptr, *p_act = nullptr;
    cudaGetSymbolAddress(&p_h, g_h);
    cudaGetSymbolAddress(&p_act, g_act);
    float* hbuf = (float*)p_h;
    float* actbuf = (float*)p_act;

    int nch = (n + 1023) / 1024;

    k_zero<<<(n + 255) / 256, 256>>>(n);
    // layer-1 GEMM depends only on x/W1
    k_gemm<<<(n + 63) / 64, 256>>>(x, W[0], hbuf, aS[0], aD[0], n, 64);

    k_hist<<<(E + 255) / 256, 256>>>(dst, E);
    k_scanA<<<nch, 256>>>(n);
    k_scanB<<<1, 32>>>(nch, n);
    k_scanC<<<nch, 256>>>(n);
    k_easum<<<256, 256>>>((const float4*)ea, E);
    k_ve<<<1, 256>>>(We[0], aE[0], We[1], aE[1], We[2], aE[2], E);
    k_scatter<<<(E + 255) / 256, 256>>>(src, dst, (const float4*)ea, E);

    int aggBlocks = (n * 32 + 255) / 256;
    for (int l = 0; l < 3; l++) {
        if (l > 0)
            k_gemm<<<(n + 63) / 64, 256>>>(actbuf, W[l], hbuf, aS[l], aD[l], n, 128);
        if (l < 2)
            k_agg<true><<<aggBlocks, 256>>>(hbuf, b[l], actbuf, n, l);
        else
            k_agg<false><<<aggBlocks, 256>>>(hbuf, b[l], actbuf, n, l);
    }

    k_loc<<<(n + 127) / 128, 128>>>(actbuf, Wl1, bl1, Wl2, bl2, out, n);
    k_pool<<<nch, 128>>>(actbuf, batch, n);
    k_class<<<NGRP, 128>>>(Wc1, bc1, Wc2, bc2, out);
}

// round 5
// speedup vs baseline: 1.2869x; 1.1108x over previous
#include <cuda_runtime.h>
#include <math.h>

#define NMAX 100000
#define EMAX 1600000
#define HCD 128
#define NGRP 64
#define NCLS 10

typedef unsigned long long ull;

// ---------------- static device scratch (zero-initialized at load; k_cleanup maintains) ----------------
__device__ float  g_h[(size_t)NMAX * HCD];
__device__ float  g_act[(size_t)NMAX * HCD];
__device__ int    g_srcs[EMAX];
__device__ float4 g_le[3][EMAX];
__device__ int    g_cnt[NMAX];          // must be 0 at kernel_launch entry (cleanup restores)
__device__ int    g_rowptr[NMAX + 1];
__device__ int    g_woff[NMAX];
__device__ int    g_sagg[256];
__device__ int    g_sflag[256];         // must be 0 at entry (cleanup restores)
__device__ float4 g_ls[NMAX];
__device__ float4 g_ld[NMAX];
__device__ float  g_ve[3 * 16 * 4];
__device__ float  g_leself[12];
__device__ float  g_easum_part[512 * 16];
__device__ float  g_gemb[NGRP * HCD];   // must be 0 at entry
__device__ float  g_gcnt[NGRP];         // must be 0 at entry

// ---------------- helpers ----------------
__device__ __forceinline__ float lrelu(float x) { return x > 0.f ? x : 0.2f * x; }
__device__ __forceinline__ float pick4(float4 v, int hd) {
    return hd == 0 ? v.x : hd == 1 ? v.y : hd == 2 ? v.z : v.w;
}
__device__ __forceinline__ ull pk2(float x, float y) {
    ull r;
    asm("mov.b64 %0, {%1,%2};" : "=l"(r) : "r"(__float_as_uint(x)), "r"(__float_as_uint(y)));
    return r;
}
__device__ __forceinline__ void fma2(ull& d, ull a, ull b) {
    asm("fma.rn.f32x2 %0, %1, %2, %0;" : "+l"(d) : "l"(a), "l"(b));
}
__device__ __forceinline__ float lo2(ull v) { return __uint_as_float((unsigned)(v & 0xffffffffull)); }
__device__ __forceinline__ float hi2(ull v) { return __uint_as_float((unsigned)(v >> 32)); }

// ============ k1: layer-1 GEMM (+fused ls/ld) AND edge hist + easum partials ============
__global__ void __launch_bounds__(256) k_gemm_hist(const float* __restrict__ A,
                                                   const float* __restrict__ W,
                                                   float* __restrict__ C,
                                                   const float* __restrict__ aS,
                                                   const float* __restrict__ aD,
                                                   int n, int K,
                                                   const int* __restrict__ dst,
                                                   const float4* __restrict__ ea4,
                                                   int E, int gemmBlocks) {
    __shared__ float As[32 * 66];
    __shared__ float Bs[32 * 128];
    __shared__ float red[64 * 8];
    int tid = threadIdx.x;

    if (blockIdx.x >= gemmBlocks) {
        // ---- hist + easum partial path ----
        int hb = blockIdx.x - gemmBlocks;
        int base = hb * 4096;
        int eend = base + 4096; if (eend > E) eend = E;
        float s[16];
#pragma unroll
        for (int f = 0; f < 16; f++) s[f] = 0.f;
        for (int e = base + tid; e < eend; e += 256) {
            atomicAdd(&g_cnt[dst[e]], 1);
#pragma unroll
            for (int q = 0; q < 4; q++) {
                float4 v = ea4[(size_t)e * 4 + q];
                s[q * 4 + 0] += v.x; s[q * 4 + 1] += v.y; s[q * 4 + 2] += v.z; s[q * 4 + 3] += v.w;
            }
        }
        float* sm16 = red;  // reuse smem
        if (tid < 16) sm16[tid] = 0.f;
        __syncthreads();
#pragma unroll
        for (int f = 0; f < 16; f++) {
            float v = s[f];
#pragma unroll
            for (int off = 16; off > 0; off >>= 1) v += __shfl_xor_sync(0xffffffffu, v, off);
            if ((tid & 31) == 0) atomicAdd(&sm16[f], v);
        }
        __syncthreads();
        if (tid < 16) g_easum_part[hb * 16 + tid] = sm16[tid];
        return;
    }

    // ---- GEMM path: 64x128 tile, 8x4 per thread, f32x2 FMAs, fused ls/ld ----
    int row0 = blockIdx.x * 64;
    int tx = tid & 31, ty = tid >> 5;
    int c0 = tx * 4;
    int r0 = ty * 8;

    for (int i = tid; i < 512; i += 256) red[i] = 0.f;

    ull acc[4][4];
#pragma unroll
    for (int p = 0; p < 4; p++)
#pragma unroll
        for (int j = 0; j < 4; j++) acc[p][j] = 0ull;

    for (int k0 = 0; k0 < K; k0 += 32) {
        int kk = tid & 31, rb = tid >> 5;
#pragma unroll
        for (int j = 0; j < 8; j++) {
            int r = rb + j * 8;
            int gr = row0 + r;
            float v = (gr < n) ? A[(size_t)gr * K + k0 + kk] : 0.f;
            As[kk * 66 + r] = v;
        }
        int nn = tid & 127;
#pragma unroll
        for (int j = 0; j < 16; j++) {
            int k2 = (tid >> 7) + j * 2;
            Bs[k2 * 128 + nn] = W[(size_t)(k0 + k2) * 128 + nn];
        }
        __syncthreads();
#pragma unroll
        for (int k = 0; k < 32; k++) {
            float4 bv = *(const float4*)&Bs[k * 128 + c0];
            ull bb0 = pk2(bv.x, bv.x);
            ull bb1 = pk2(bv.y, bv.y);
            ull bb2 = pk2(bv.z, bv.z);
            ull bb3 = pk2(bv.w, bv.w);
            const ull* a2 = (const ull*)&As[k * 66 + r0];
#pragma unroll
            for (int p = 0; p < 4; p++) {
                ull av = a2[p];
                fma2(acc[p][0], av, bb0);
                fma2(acc[p][1], av, bb1);
                fma2(acc[p][2], av, bb2);
                fma2(acc[p][3], av, bb3);
            }
        }
        __syncthreads();
    }

    int hd = tx >> 3;
    float as4[4], ad4[4];
#pragma unroll
    for (int j = 0; j < 4; j++) { as4[j] = aS[c0 + j]; ad4[j] = aD[c0 + j]; }
#pragma unroll
    for (int p = 0; p < 4; p++) {
        float sSlo = 0.f, sShi = 0.f, sDlo = 0.f, sDhi = 0.f;
#pragma unroll
        for (int j = 0; j < 4; j++) {
            float lo = lo2(acc[p][j]), hi = hi2(acc[p][j]);
            sSlo += lo * as4[j]; sShi += hi * as4[j];
            sDlo += lo * ad4[j]; sDhi += hi * ad4[j];
        }
        int r = r0 + 2 * p;
        atomicAdd(&red[r * 8 + hd], sSlo);
        atomicAdd(&red[r * 8 + 4 + hd], sDlo);
        atomicAdd(&red[(r + 1) * 8 + hd], sShi);
        atomicAdd(&red[(r + 1) * 8 + 4 + hd], sDhi);
    }

#pragma unroll
    for (int p = 0; p < 4; p++) {
        int r = row0 + r0 + 2 * p;
        if (r < n) {
            float4 v = make_float4(lo2(acc[p][0]), lo2(acc[p][1]), lo2(acc[p][2]), lo2(acc[p][3]));
            *(float4*)&C[(size_t)r * 128 + c0] = v;
        }
        if (r + 1 < n) {
            float4 v = make_float4(hi2(acc[p][0]), hi2(acc[p][1]), hi2(acc[p][2]), hi2(acc[p][3]));
            *(float4*)&C[(size_t)(r + 1) * 128 + c0] = v;
        }
    }

    __syncthreads();
    if (tid < 128) {
        int r = tid >> 1;
        int which = tid & 1;
        int gr = row0 + r;
        if (gr < n) {
            float4 v = *(const float4*)&red[r * 8 + which * 4];
            if (which == 0) g_ls[gr] = v; else g_ld[gr] = v;
        }
    }
}

// ============ k2: single-launch decoupled-lookback scan + (block 0) ve/leself ============
__global__ void __launch_bounds__(256) k_scan_ve(int n, int nHist,
                                                 const float* We1, const float* aE1,
                                                 const float* We2, const float* aE2,
                                                 const float* We3, const float* aE3, int E) {
    __shared__ int sh[256];
    __shared__ int sh2[256];
    int tid = threadIdx.x;
    int b = blockIdx.x;
    int base = b * 1024 + tid * 4;
    int v[4];
#pragma unroll
    for (int j = 0; j < 4; j++) { int idx = base + j; v[j] = (idx < n) ? g_cnt[idx] : 0; }
    int s = v[0] + v[1] + v[2] + v[3];
    sh[tid] = s; __syncthreads();
    for (int d = 1; d < 256; d <<= 1) {
        int add = (tid >= (unsigned)d) ? sh[tid - d] : 0;
        __syncthreads();
        sh[tid] += add;
        __syncthreads();
    }
    // publish block aggregate
    if (tid == 0) {
        g_sagg[b] = sh[255];
        __threadfence();
        atomicExch(&g_sflag[b], 1);
    }
    // lookback: sum aggregates of all predecessor blocks (each published independently)
    int pre = 0;
    {
        volatile int* vf = (volatile int*)g_sflag;
        volatile int* va = (volatile int*)g_sagg;
        for (int i = tid; i < b; i += 256) {
            while (vf[i] == 0) { }
            pre += va[i];
        }
    }
    __threadfence();
    sh2[tid] = pre; __syncthreads();
    for (int d = 128; d > 0; d >>= 1) {
        if (tid < d) sh2[tid] += sh2[tid + d];
        __syncthreads();
    }
    int blockPre = sh2[0];
    int off = blockPre + sh[tid] - s;
#pragma unroll
    for (int j = 0; j < 4; j++) {
        int idx = base + j;
        if (idx < n) { g_rowptr[idx] = off; g_woff[idx] = off; off += v[j]; }
    }
    if (b == gridDim.x - 1 && tid == 255) g_rowptr[n] = blockPre + sh[255];

    // ---- block 0: reduce easum partials, compute ve + leself ----
    if (b == 0) {
        __shared__ float easum[16];
        if (tid < 16) {
            float t = 0.f;
            for (int i = 0; i < nHist; i++) t += g_easum_part[i * 16 + tid];
            easum[tid] = t;
        }
        __syncthreads();
        const float* Wes[3] = { We1, We2, We3 };
        const float* aEs[3] = { aE1, aE2, aE3 };
        if (tid < 192) {
            int l = tid >> 6, f = (tid >> 2) & 15, h = tid & 3;
            const float* We = Wes[l]; const float* aE = aEs[l];
            float t = 0.f;
            for (int c = 0; c < 32; c++) t += We[f * 128 + h * 32 + c] * aE[h * 32 + c];
            g_ve[l * 64 + f * 4 + h] = t;
        }
        __syncthreads();
        if (tid < 12) {
            int l = tid >> 2, h = tid & 3;
            float inv = 1.f / (float)E;
            float t = 0.f;
            for (int f = 0; f < 16; f++) t += easum[f] * inv * g_ve[l * 64 + f * 4 + h];
            g_leself[l * 4 + h] = t;
        }
    }
}

// ============ k3: scatter edges to CSR + per-edge le for 3 layers ============
__global__ void k_scatter(const int* __restrict__ src, const int* __restrict__ dst,
                          const float4* __restrict__ ea4, int E) {
    int e = blockIdx.x * blockDim.x + threadIdx.x;
    if (e >= E) return;
    int d = dst[e];
    int pos = atomicAdd(&g_woff[d], 1);
    g_srcs[pos] = src[e];
    float a[16];
#pragma unroll
    for (int q = 0; q < 4; q++) {
        float4 v = ea4[(size_t)e * 4 + q];
        a[q * 4 + 0] = v.x; a[q * 4 + 1] = v.y; a[q * 4 + 2] = v.z; a[q * 4 + 3] = v.w;
    }
#pragma unroll
    for (int l = 0; l < 3; l++) {
        const float4* vel = (const float4*)&g_ve[l * 64];
        float r0 = 0.f, r1 = 0.f, r2 = 0.f, r3 = 0.f;
#pragma unroll
        for (int f = 0; f < 16; f++) {
            float4 vv = __ldg(&vel[f]);
            float av = a[f];
            r0 += av * vv.x; r1 += av * vv.y; r2 += av * vv.z; r3 += av * vv.w;
        }
        g_le[l][pos] = make_float4(r0, r1, r2, r3);
    }
}

// ============ plain GEMM (layers 2/3) with fused ls/ld ============
__global__ void __launch_bounds__(256) k_gemm(const float* __restrict__ A,
                                              const float* __restrict__ W,
                                              float* __restrict__ C,
                                              const float* __restrict__ aS,
                                              const float* __restrict__ aD,
                                              int n, int K) {
    __shared__ float As[32 * 66];
    __shared__ float Bs[32 * 128];
    __shared__ float red[64 * 8];
    int tid = threadIdx.x;
    int row0 = blockIdx.x * 64;
    int tx = tid & 31, ty = tid >> 5;
    int c0 = tx * 4;
    int r0 = ty * 8;

    for (int i = tid; i < 512; i += 256) red[i] = 0.f;

    ull acc[4][4];
#pragma unroll
    for (int p = 0; p < 4; p++)
#pragma unroll
        for (int j = 0; j < 4; j++) acc[p][j] = 0ull;

    for (int k0 = 0; k0 < K; k0 += 32) {
        int kk = tid & 31, rb = tid >> 5;
#pragma unroll
        for (int j = 0; j < 8; j++) {
            int r = rb + j * 8;
            int gr = row0 + r;
            float v = (gr < n) ? A[(size_t)gr * K + k0 + kk] : 0.f;
            As[kk * 66 + r] = v;
        }
        int nn = tid & 127;
#pragma unroll
        for (int j = 0; j < 16; j++) {
            int k2 = (tid >> 7) + j * 2;
            Bs[k2 * 128 + nn] = W[(size_t)(k0 + k2) * 128 + nn];
        }
        __syncthreads();
#pragma unroll
        for (int k = 0; k < 32; k++) {
            float4 bv = *(const float4*)&Bs[k * 128 + c0];
            ull bb0 = pk2(bv.x, bv.x);
            ull bb1 = pk2(bv.y, bv.y);
            ull bb2 = pk2(bv.z, bv.z);
            ull bb3 = pk2(bv.w, bv.w);
            const ull* a2 = (const ull*)&As[k * 66 + r0];
#pragma unroll
            for (int p = 0; p < 4; p++) {
                ull av = a2[p];
                fma2(acc[p][0], av, bb0);
                fma2(acc[p][1], av, bb1);
                fma2(acc[p][2], av, bb2);
                fma2(acc[p][3], av, bb3);
            }
        }
        __syncthreads();
    }

    int hd = tx >> 3;
    float as4[4], ad4[4];
#pragma unroll
    for (int j = 0; j < 4; j++) { as4[j] = aS[c0 + j]; ad4[j] = aD[c0 + j]; }
#pragma unroll
    for (int p = 0; p < 4; p++) {
        float sSlo = 0.f, sShi = 0.f, sDlo = 0.f, sDhi = 0.f;
#pragma unroll
        for (int j = 0; j < 4; j++) {
            float lo = lo2(acc[p][j]), hi = hi2(acc[p][j]);
            sSlo += lo * as4[j]; sShi += hi * as4[j];
            sDlo += lo * ad4[j]; sDhi += hi * ad4[j];
        }
        int r = r0 + 2 * p;
        atomicAdd(&red[r * 8 + hd], sSlo);
        atomicAdd(&red[r * 8 + 4 + hd], sDlo);
        atomicAdd(&red[(r + 1) * 8 + hd], sShi);
        atomicAdd(&red[(r + 1) * 8 + 4 + hd], sDhi);
    }

#pragma unroll
    for (int p = 0; p < 4; p++) {
        int r = row0 + r0 + 2 * p;
        if (r < n) {
            float4 v = make_float4(lo2(acc[p][0]), lo2(acc[p][1]), lo2(acc[p][2]), lo2(acc[p][3]));
            *(float4*)&C[(size_t)r * 128 + c0] = v;
        }
        if (r + 1 < n) {
            float4 v = make_float4(hi2(acc[p][0]), hi2(acc[p][1]), hi2(acc[p][2]), hi2(acc[p][3]));
            *(float4*)&C[(size_t)(r + 1) * 128 + c0] = v;
        }
    }

    __syncthreads();
    if (tid < 128) {
        int r = tid >> 1;
        int which = tid & 1;
        int gr = row0 + r;
        if (gr < n) {
            float4 v = *(const float4*)&red[r * 8 + which * 4];
            if (which == 0) g_ls[gr] = v; else g_ld[gr] = v;
        }
    }
}

// ============ single-pass agg: chunked lane-parallel exp + smem-staged gather ============
template <bool ELU>
__global__ void __launch_bounds__(256) k_agg(const float* __restrict__ h,
                                             const float* __restrict__ bias,
                                             float* __restrict__ out, int n, int layer) {
    __shared__ int    sS[8][32];
    __shared__ float4 sT[8][32];
    int wib = threadIdx.x >> 5;
    int lane = threadIdx.x & 31;
    int w = (blockIdx.x * blockDim.x + threadIdx.x) >> 5;
    if (w >= n) return;
    int beg = g_rowptr[w], end = g_rowptr[w + 1];
    float4 ldv = g_ld[w];
    float4 lsv = g_ls[w];
    float4 lself = *(const float4*)&g_leself[layer * 4];
    const float4* le = g_le[layer];
    int hd = lane >> 3;

    float4 exs;
    exs.x = __expf(lrelu(lsv.x + ldv.x + lself.x));
    exs.y = __expf(lrelu(lsv.y + ldv.y + lself.y));
    exs.z = __expf(lrelu(lsv.z + ldv.z + lself.z));
    exs.w = __expf(lrelu(lsv.w + ldv.w + lself.w));

    float4 hv = __ldg((const float4*)(h + (size_t)w * 128) + lane);
    float exmy = pick4(exs, hd);
    float4 acc = make_float4(exmy * hv.x, exmy * hv.y, exmy * hv.z, exmy * hv.w);
    float4 dpart = (lane == 0) ? exs : make_float4(0.f, 0.f, 0.f, 0.f);

    for (int base = beg; base < end; base += 32) {
        int m = end - base;
        if (m > 32) m = 32;
        int s = 0;
        float4 t = make_float4(0.f, 0.f, 0.f, 0.f);
        if (lane < m) {
            int i = base + lane;
            s = __ldg(&g_srcs[i]);
            float4 l4 = __ldg(&g_ls[s]);
            float4 e4 = __ldg(&le[i]);
            t.x = __expf(lrelu(l4.x + ldv.x + e4.x));
            t.y = __expf(lrelu(l4.y + ldv.y + e4.y));
            t.z = __expf(lrelu(l4.z + ldv.z + e4.z));
            t.w = __expf(lrelu(l4.w + ldv.w + e4.w));
        }
        dpart.x += t.x; dpart.y += t.y; dpart.z += t.z; dpart.w += t.w;
        sS[wib][lane] = s;
        sT[wib][lane] = t;
        __syncwarp();
#pragma unroll 4
        for (int j = 0; j < m; j++) {
            int sj = sS[wib][j];
            float tj = ((const float*)&sT[wib][j])[hd];
            float4 hj = __ldg((const float4*)(h + (size_t)sj * 128) + lane);
            acc.x += tj * hj.x;
            acc.y += tj * hj.y;
            acc.z += tj * hj.z;
            acc.w += tj * hj.w;
        }
        __syncwarp();
    }

#pragma unroll
    for (int off = 16; off > 0; off >>= 1) {
        dpart.x += __shfl_xor_sync(0xffffffffu, dpart.x, off);
        dpart.y += __shfl_xor_sync(0xffffffffu, dpart.y, off);
        dpart.z += __shfl_xor_sync(0xffffffffu, dpart.z, off);
        dpart.w += __shfl_xor_sync(0xffffffffu, dpart.w, off);
    }
    float den = pick4(dpart, hd) + 1e-16f;
    float inv = 1.f / den;
    float4 b4 = __ldg((const float4*)bias + lane);
    float4 o;
    o.x = acc.x * inv + b4.x;
    o.y = acc.y * inv + b4.y;
    o.z = acc.z * inv + b4.z;
    o.w = acc.w * inv + b4.w;
    if (ELU) {
        o.x = o.x > 0.f ? o.x : (__expf(o.x) - 1.f);
        o.y = o.y > 0.f ? o.y : (__expf(o.y) - 1.f);
        o.z = o.z > 0.f ? o.z : (__expf(o.z) - 1.f);
        o.w = o.w > 0.f ? o.w : (__expf(o.w) - 1.f);
    }
    *((float4*)(out + (size_t)w * 128) + lane) = o;
}

// ============ node head (f32x2 over the 64-dim) ============
__global__ void __launch_bounds__(128) k_loc(const float* __restrict__ h,
                                             const float* __restrict__ Wl1, const float* __restrict__ bl1,
                                             const float* __restrict__ Wl2, const float* __restrict__ bl2,
                                             float* __restrict__ out, int n) {
    __shared__ ull  W1s2[128 * 32];  // (Wl1[c][2j], Wl1[c][2j+1]) pairs
    __shared__ float W2s[64];
    __shared__ ull  b1s2[32];
    for (int i = threadIdx.x; i < 128 * 32; i += 128) W1s2[i] = ((const ull*)Wl1)[i];
    if (threadIdx.x < 64) W2s[threadIdx.x] = Wl2[threadIdx.x];
    if (threadIdx.x < 32) b1s2[threadIdx.x] = ((const ull*)bl1)[threadIdx.x];
    __syncthreads();
    int nd = blockIdx.x * 128 + threadIdx.x;
    if (nd >= n) return;
    ull t2[32];
#pragma unroll
    for (int j = 0; j < 32; j++) t2[j] = b1s2[j];
    const float* hr = h + (size_t)nd * 128;
    for (int c = 0; c < 128; c++) {
        float hvf = hr[c];
        ull hv2 = pk2(hvf, hvf);
        const ulonglong2* w2 = (const ulonglong2*)&W1s2[c * 32];
#pragma unroll
        for (int j2 = 0; j2 < 16; j2++) {
            ulonglong2 ww = w2[j2];
            fma2(t2[2 * j2], hv2, ww.x);
            fma2(t2[2 * j2 + 1], hv2, ww.y);
        }
    }
    float o = bl2[0];
#pragma unroll
    for (int j = 0; j < 32; j++) {
        o += fmaxf(lo2(t2[j]), 0.f) * W2s[2 * j];
        o += fmaxf(hi2(t2[j]), 0.f) * W2s[2 * j + 1];
    }
    out[640 + nd] = o;
}

__global__ void k_pool(const float* __restrict__ h, const int* __restrict__ batch, int n) {
    int base = blockIdx.x * 1024;
    int tid = threadIdx.x;
    int endr = min(base + 1024, n);
    float acc = 0.f; int cur = -1; int cnt = 0;
    for (int r = base; r < endr; r++) {
        int g = batch[r];
        if (g != cur) {
            if (cur >= 0) {
                atomicAdd(&g_gemb[cur * 128 + tid], acc);
                if (tid == 0) atomicAdd(&g_gcnt[cur], (float)cnt);
            }
            acc = 0.f; cnt = 0; cur = g;
        }
        acc += h[(size_t)r * 128 + tid];
        cnt++;
    }
    if (cur >= 0) {
        atomicAdd(&g_gemb[cur * 128 + tid], acc);
        if (tid == 0) atomicAdd(&g_gcnt[cur], (float)cnt);
    }
}

__global__ void __launch_bounds__(128) k_class(const float* __restrict__ Wc1, const float* __restrict__ bc1,
                                               const float* __restrict__ Wc2, const float* __restrict__ bc2,
                                               float* __restrict__ out) {
    __shared__ float e[128];
    __shared__ float t[128];
    int g = blockIdx.x, tid = threadIdx.x;
    float cnt = fmaxf(g_gcnt[g], 1.f);
    e[tid] = g_gemb[g * 128 + tid] / cnt;
    __syncthreads();
    float s = bc1[tid];
    for (int c = 0; c < 128; c++) s += e[c] * Wc1[c * 128 + tid];
    t[tid] = fmaxf(s, 0.f);
    __syncthreads();
    if (tid < NCLS) {
        float o = bc2[tid];
        for (int c = 0; c < 128; c++) o += t[c] * Wc2[c * NCLS + tid];
        out[g * NCLS + tid] = o;
    }
}

// ============ trailing cleanup: restore zero-invariant for next replay ============
__global__ void k_cleanup(int n) {
    int i = blockIdx.x * blockDim.x + threadIdx.x;
    if (i < n) g_cnt[i] = 0;
    if (i < NGRP * HCD) g_gemb[i] = 0.f;
    if (i < NGRP) g_gcnt[i] = 0.f;
    if (i < 256) g_sflag[i] = 0;
}

// ---------------- launch ----------------
extern "C" void kernel_launch(void* const* d_in, const int* in_sizes, int n_in,
                              void* d_out, int out_size) {
    const float* x       = (const float*)d_in[0];
    const int*   ei      = (const int*)d_in[1];
    const float* ea      = (const float*)d_in[2];
    const int*   batch   = (const int*)d_in[3];
    const float* W[3], *aS[3], *aD[3], *We[3], *aE[3], *b[3];
    int p = 4;
    for (int l = 0; l < 3; l++) {
        W[l]  = (const float*)d_in[p++];
        aS[l] = (const float*)d_in[p++];
        aD[l] = (const float*)d_in[p++];
        We[l] = (const float*)d_in[p++];
        aE[l] = (const float*)d_in[p++];
        b[l]  = (const float*)d_in[p++];
    }
    const float* Wc1 = (const float*)d_in[22];
    const float* bc1 = (const float*)d_in[23];
    const float* Wc2 = (const float*)d_in[24];
    const float* bc2 = (const float*)d_in[25];
    const float* Wl1 = (const float*)d_in[26];
    const float* bl1 = (const float*)d_in[27];
    const float* Wl2 = (const float*)d_in[28];
    const float* bl2 = (const float*)d_in[29];

    int n = in_sizes[0] / 64;
    int E = in_sizes[1] / 2;
    const int* src = ei;
    const int* dst = ei + E;
    float* out = (float*)d_out;

    void *p_h = nullptr, *p_act = nullptr;
    cudaGetSymbolAddress(&p_h, g_h);
    cudaGetSymbolAddress(&p_act, g_act);
    float* hbuf = (float*)p_h;
    float* actbuf = (float*)p_act;

    int gemmBlocks = (n + 63) / 64;
    int histBlocks = (E + 4095) / 4096;
    int scanBlocks = (n + 1023) / 1024;
    int aggBlocks = (n * 32 + 255) / 256;

    // 1: layer-1 GEMM + hist + easum (g_cnt zero-invariant holds at entry)
    k_gemm_hist<<<gemmBlocks + histBlocks, 256>>>(x, W[0], hbuf, aS[0], aD[0], n, 64,
                                                  dst, (const float4*)ea, E, gemmBlocks);
    // 2: scan + ve/leself
    k_scan_ve<<<scanBlocks, 256>>>(n, histBlocks, We[0], aE[0], We[1], aE[1], We[2], aE[2], E);
    // 3: scatter
    k_scatter<<<(E + 255) / 256, 256>>>(src, dst, (const float4*)ea, E);
    // 4: agg layer 0  (profiled launch)
    k_agg<true><<<aggBlocks, 256>>>(hbuf, b[0], actbuf, n, 0);
    // 5-8: layers 2,3
    k_gemm<<<gemmBlocks, 256>>>(actbuf, W[1], hbuf, aS[1], aD[1], n, 128);
    k_agg<true><<<aggBlocks, 256>>>(hbuf, b[1], actbuf, n, 1);
    k_gemm<<<gemmBlocks, 256>>>(actbuf, W[2], hbuf, aS[2], aD[2], n, 128);
    k_agg<false><<<aggBlocks, 256>>>(hbuf, b[2], actbuf, n, 2);
    // heads
    k_loc<<<(n + 127) / 128, 128>>>(actbuf, Wl1, bl1, Wl2, bl2, out, n);
    k_pool<<<scanBlocks, 128>>>(actbuf, batch, n);
    k_class<<<NGRP, 128>>>(Wc1, bc1, Wc2, bc2, out);
    // cleanup: restore zero-invariant
    k_cleanup<<<(n + 255) / 256, 256>>>(n);
}